// round 9
// baseline (speedup 1.0000x reference)
#include <cuda_runtime.h>
#include <cuda_fp16.h>
#include <cstdint>
#include <cstddef>

// ---------------- problem constants ----------------
// B=256, K=16, H=64, W=64, N=1024, F_IN=143 (=144 with zero drop), HID=128, NCLS=16

// ---------------- device scratch ----------------
__device__ __align__(16) __half   g_zh[16u * 64u * 64u * 256u];  // (k,i,j,b) fp16 of z/15
__device__ __align__(16) uint32_t g_w1p[16 * 9792];              // [v][kp<72, stride 136][h<128] half2(f=2kp,2kp+1)
__device__ __align__(16) uint32_t g_w2p[1024];                   // [kp<64][c<16] half2
__device__ int g_counter;
__device__ int g_done;

// ---------------- helpers ----------------
__device__ __forceinline__ uint32_t pack_half2(float lo, float hi) {
    __half2 h = __floats2half2_rn(lo, hi);
    return *reinterpret_cast<uint32_t*>(&h);
}
__device__ __forceinline__ uint32_t pack_us(unsigned short lo, unsigned short hi) {
    return (uint32_t)lo | ((uint32_t)hi << 16);
}
__device__ __forceinline__ void mma16816(float* c,
                                         uint32_t a0, uint32_t a1, uint32_t a2, uint32_t a3,
                                         uint32_t b0, uint32_t b1) {
    asm volatile("mma.sync.aligned.m16n8k16.row.col.f32.f16.f16.f32 "
                 "{%0,%1,%2,%3}, {%4,%5,%6,%7}, {%8,%9}, {%0,%1,%2,%3};"
                 : "+f"(c[0]), "+f"(c[1]), "+f"(c[2]), "+f"(c[3])
                 : "r"(a0), "r"(a1), "r"(a2), "r"(a3), "r"(b0), "r"(b1));
}

// ---------------- prep: z transpose + weight packs + counter reset ----------------
// blocks 0..1023: z (B,K,H,W) int32 -> g_zh (K,H,W,B) fp16(z/15).  blocks 1024..1103: weights.
__global__ void __launch_bounds__(256) prep_all(const int* __restrict__ z,
                                                const float* __restrict__ W1,
                                                const float* __restrict__ W2) {
    __shared__ __half tile[64][264];
    if (blockIdx.x < 1024) {
        const int k = blockIdx.x >> 6, i = blockIdx.x & 63;
        const int t = threadIdx.x;
        const int j = t & 63, b0 = t >> 6;
        const int* src = z + k * 4096 + i * 64 + j;
#pragma unroll 8
        for (int it = 0; it < 64; it++) {
            int b = b0 * 64 + it;
            tile[j][b] = __float2half((float)src[(size_t)b << 16] * (1.0f / 15.0f));
        }
        __syncthreads();
        __half* dst = g_zh + ((size_t)k << 20) + ((size_t)i << 14);
#pragma unroll
        for (int it = 0; it < 8; it++) {
            int w = t + (it << 8);
            int jo = w >> 5, q = w & 31;
            uint4 v = *reinterpret_cast<const uint4*>(&tile[jo][q * 8]);
            *reinterpret_cast<uint4*>(dst + jo * 256 + q * 8) = v;
        }
    } else {
        const int tx = (blockIdx.x - 1024) * 256 + threadIdx.x;   // 0..20479
        if (tx == 0) { g_counter = 0; g_done = 0; }
        for (int i = tx; i < 147456; i += 20480) {                // 16v x 72kp x 128h
            int v = i / 9216;
            int r = i - v * 9216;
            int kp = r >> 7, h = r & 127;
            int drop = 64 + v;
            int f0 = 2 * kp, f1 = 2 * kp + 1;
            float x0 = (f0 == drop) ? 0.f : W1[(f0 - (f0 > drop)) * 128 + h];
            float x1 = (f1 == drop) ? 0.f : W1[(f1 - (f1 > drop)) * 128 + h];
            g_w1p[v * 9792 + kp * 136 + h] = pack_half2(x0, x1);
        }
        if (tx < 1024) {
            int kp = tx >> 4, c = tx & 15;
            g_w2p[tx] = pack_half2(W2[(2 * kp) * 16 + c], W2[(2 * kp + 1) * 16 + c]);
        }
    }
}

// ---------------- main kernel ----------------
// grid 1024 (one CTA per n). 8 warps, each warp owns M=32 b-rows (two m16 tiles).
__global__ void __launch_bounds__(256, 1)
main_kernel(const int* __restrict__ z, const int* __restrict__ bs,
            const int* __restrict__ ii, const int* __restrict__ jj,
            const float* __restrict__ b1, const float* __restrict__ b2,
            float* __restrict__ out)
{
    __shared__ __align__(16) uint32_t w1s[9792];   // [kp stride 136][h] — conflict-free B-frag reads
    __shared__ __align__(16) uint32_t w2s[1024];
    __shared__ float b1s[128];
    __shared__ float b2s[16];
    __shared__ int   ered[8];

    const int tid  = threadIdx.x;
    const int lane = tid & 31;
    const int wm   = tid >> 5;
    const int tig  = lane & 3;
    const int gid  = lane >> 2;
    const int n = blockIdx.x;

    const int bsv = __ldg(bs + n), iiv = __ldg(ii + n), jjv = __ldg(jj + n);

    // ---- stage weights/biases ----
    {
        const uint4* s1 = reinterpret_cast<const uint4*>(g_w1p + (size_t)bsv * 9792);
        uint4* d1 = reinterpret_cast<uint4*>(w1s);
        for (int i = tid; i < 2448; i += 256) d1[i] = s1[i];
        reinterpret_cast<uint4*>(w2s)[tid] = reinterpret_cast<const uint4*>(g_w2p)[tid];
        if (tid < 128) b1s[tid] = b1[tid];
        if (tid < 16)  b2s[tid] = b2[tid];
    }
    __syncthreads();

    // ---- MMA1: two m16 tiles per warp.  c0: rows b_lo/b_lo+8, c1: rows b_lo+16/b_lo+24 ----
    float c0[16][4], c1[16][4];
#pragma unroll
    for (int t = 0; t < 16; t++) {
#pragma unroll
        for (int q = 0; q < 4; q++) { c0[t][q] = 0.f; c1[t][q] = 0.f; }
    }

    const int b_lo = wm * 32 + gid;
    const int k0 = 2 * tig;
    const unsigned short* zh = reinterpret_cast<const unsigned short*>(g_zh);

#pragma unroll
    for (int s = 0; s < 9; s++) {
        const int ni = (iiv + (s / 3) + 63) & 63;
        const int nj = (jjv + (s % 3) + 63) & 63;
        const unsigned short* p = zh + (((size_t)ni << 14) + ((size_t)nj << 8));
        const size_t o0 = (size_t)k0 << 20,       o1 = (size_t)(k0 + 1) << 20;
        const size_t o8 = (size_t)(k0 + 8) << 20, o9 = (size_t)(k0 + 9) << 20;
        // tile A (rows b_lo, b_lo+8)
        uint32_t a0 = pack_us(p[o0 + b_lo],      p[o1 + b_lo]);
        uint32_t a1 = pack_us(p[o0 + b_lo + 8],  p[o1 + b_lo + 8]);
        uint32_t a2 = pack_us(p[o8 + b_lo],      p[o9 + b_lo]);
        uint32_t a3 = pack_us(p[o8 + b_lo + 8],  p[o9 + b_lo + 8]);
        // tile B (rows b_lo+16, b_lo+24)
        uint32_t e0 = pack_us(p[o0 + b_lo + 16], p[o1 + b_lo + 16]);
        uint32_t e1 = pack_us(p[o0 + b_lo + 24], p[o1 + b_lo + 24]);
        uint32_t e2 = pack_us(p[o8 + b_lo + 16], p[o9 + b_lo + 16]);
        uint32_t e3 = pack_us(p[o8 + b_lo + 24], p[o9 + b_lo + 24]);

        const uint32_t* w0 = w1s + (8 * s + tig) * 136 + gid;
        const uint32_t* w4 = w0 + 4 * 136;
#pragma unroll
        for (int t = 0; t < 16; t++) {
            uint32_t bb0 = w0[8 * t];
            uint32_t bb1 = w4[8 * t];
            mma16816(c0[t], a0, a1, a2, a3, bb0, bb1);
            mma16816(c1[t], e0, e1, e2, e3, bb0, bb1);
        }
    }

    // ---- layer 2: h = relu(c + b1) chained as A-frags; shared W2 B-frags ----
    float dA0[4] = {0.f, 0.f, 0.f, 0.f}, dA1[4] = {0.f, 0.f, 0.f, 0.f};
    float dB0[4] = {0.f, 0.f, 0.f, 0.f}, dB1[4] = {0.f, 0.f, 0.f, 0.f};
#pragma unroll
    for (int s = 0; s < 8; s++) {
        float2 bbl = reinterpret_cast<const float2*>(b1s)[8 * s + tig];
        float2 bbh = reinterpret_cast<const float2*>(b1s)[8 * s + tig + 4];
        uint32_t a0 = pack_half2(fmaxf(c0[2 * s][0] + bbl.x, 0.f),     fmaxf(c0[2 * s][1] + bbl.y, 0.f));
        uint32_t a1 = pack_half2(fmaxf(c0[2 * s][2] + bbl.x, 0.f),     fmaxf(c0[2 * s][3] + bbl.y, 0.f));
        uint32_t a2 = pack_half2(fmaxf(c0[2 * s + 1][0] + bbh.x, 0.f), fmaxf(c0[2 * s + 1][1] + bbh.y, 0.f));
        uint32_t a3 = pack_half2(fmaxf(c0[2 * s + 1][2] + bbh.x, 0.f), fmaxf(c0[2 * s + 1][3] + bbh.y, 0.f));
        uint32_t e0 = pack_half2(fmaxf(c1[2 * s][0] + bbl.x, 0.f),     fmaxf(c1[2 * s][1] + bbl.y, 0.f));
        uint32_t e1 = pack_half2(fmaxf(c1[2 * s][2] + bbl.x, 0.f),     fmaxf(c1[2 * s][3] + bbl.y, 0.f));
        uint32_t e2 = pack_half2(fmaxf(c1[2 * s + 1][0] + bbh.x, 0.f), fmaxf(c1[2 * s + 1][1] + bbh.y, 0.f));
        uint32_t e3 = pack_half2(fmaxf(c1[2 * s + 1][2] + bbh.x, 0.f), fmaxf(c1[2 * s + 1][3] + bbh.y, 0.f));

        uint32_t b00 = w2s[(8 * s + tig) * 16 + gid];
        uint32_t b01 = w2s[(8 * s + tig + 4) * 16 + gid];
        uint32_t b10 = w2s[(8 * s + tig) * 16 + 8 + gid];
        uint32_t b11 = w2s[(8 * s + tig + 4) * 16 + 8 + gid];
        mma16816(dA0, a0, a1, a2, a3, b00, b01);
        mma16816(dA1, a0, a1, a2, a3, b10, b11);
        mma16816(dB0, e0, e1, e2, e3, b00, b01);
        mma16816(dB1, e0, e1, e2, e3, b10, b11);
    }

    // ---- epilogue: argmax per row (4 rows per thread-group), count errors ----
    float2 q0 = reinterpret_cast<const float2*>(b2s)[tig];
    float2 q1 = reinterpret_cast<const float2*>(b2s)[tig + 4];

    float bv[4]; int bi[4];
    {
        const float* d0[2] = { dA0, dB0 };
        const float* d1[2] = { dA1, dB1 };
#pragma unroll
        for (int tb = 0; tb < 2; tb++) {
#pragma unroll
            for (int hr = 0; hr < 2; hr++) {                 // row lo (+0/+16) / hi (+8/+24)
                float v0 = d0[tb][2 * hr]     + q0.x;
                float v1 = d0[tb][2 * hr + 1] + q0.y;
                float v2 = d1[tb][2 * hr]     + q1.x;
                float v3 = d1[tb][2 * hr + 1] + q1.y;
                float best = v0; int idx = 2 * tig;
                if (v1 > best) { best = v1; idx = 2 * tig + 1; }
                if (v2 > best) { best = v2; idx = 8 + 2 * tig; }
                if (v3 > best) { best = v3; idx = 9 + 2 * tig; }
                bv[tb * 2 + hr] = best; bi[tb * 2 + hr] = idx;
            }
        }
    }
#pragma unroll
    for (int off = 1; off <= 2; off <<= 1) {
#pragma unroll
        for (int r = 0; r < 4; r++) {
            float ov = __shfl_xor_sync(0xffffffffu, bv[r], off);
            int   oi = __shfl_xor_sync(0xffffffffu, bi[r], off);
            if (ov > bv[r] || (ov == bv[r] && oi < bi[r])) { bv[r] = ov; bi[r] = oi; }
        }
    }

    unsigned errs = 0;
    if (tig == 0) {
        const size_t toff = (size_t)bsv * 4096 + (size_t)iiv * 64 + jjv;
        // rows: b_lo (tile A lo), b_lo+8 (A hi), b_lo+16 (B lo), b_lo+24 (B hi)
        int t0 = __ldg(z + ((size_t)(b_lo)      << 16) + toff);
        int t1 = __ldg(z + ((size_t)(b_lo + 8)  << 16) + toff);
        int t2 = __ldg(z + ((size_t)(b_lo + 16) << 16) + toff);
        int t3 = __ldg(z + ((size_t)(b_lo + 24) << 16) + toff);
        errs = (unsigned)(bi[0] != t0) + (unsigned)(bi[1] != t1)
             + (unsigned)(bi[2] != t2) + (unsigned)(bi[3] != t3);
    }
    unsigned wtot = __reduce_add_sync(0xffffffffu, errs);
    if (lane == 0) ered[wm] = (int)wtot;
    __syncthreads();
    if (tid == 0) {
        int tot = 0;
#pragma unroll
        for (int w = 0; w < 8; w++) tot += ered[w];
        atomicAdd(&g_counter, tot);
        __threadfence();
        int done = atomicAdd(&g_done, 1);
        if (done == (int)gridDim.x - 1) {
            int cnt = atomicAdd(&g_counter, 0);
            out[0] = (float)cnt * (1.0f / 262144.0f);     // N*B = 2^18
        }
    }
}

// ---------------- launch ----------------
extern "C" void kernel_launch(void* const* d_in, const int* in_sizes, int n_in,
                              void* d_out, int out_size) {
    (void)in_sizes; (void)n_in; (void)out_size;
    const int*   z  = (const int*)d_in[0];
    const int*   bs = (const int*)d_in[1];
    const int*   ii = (const int*)d_in[2];
    const int*   jj = (const int*)d_in[3];
    const float* W1 = (const float*)d_in[4];
    const float* b1 = (const float*)d_in[5];
    const float* W2 = (const float*)d_in[6];
    const float* b2 = (const float*)d_in[7];

    prep_all<<<1104, 256>>>(z, W1, W2);
    main_kernel<<<1024, 256>>>(z, bs, ii, jj, b1, b2, (float*)d_out);
}

// round 13
// speedup vs baseline: 1.0675x; 1.0675x over previous
#include <cuda_runtime.h>
#include <cuda_fp16.h>
#include <cstdint>
#include <cstddef>

// ---------------- problem constants ----------------
// B=256, K=16, H=64, W=64, N=1024, F_IN=143 (=144 with zero drop), HID=128, NCLS=16

// ---------------- device scratch ----------------
__device__ __align__(16) __half   g_zt[64u * 64u * 256u * 16u];  // (i,j,b,k) fp16 of z/15 — k fastest (32B rows)
__device__ __align__(16) uint32_t g_w1p[16 * 9504];              // [v][kp<72, stride 132][m<128] permuted W1 packs
__device__ __align__(16) uint32_t g_w2p[1024];                   // [kp<64][c<16] half2
__device__ int g_counter;
__device__ int g_done;

// ---------------- helpers ----------------
__device__ __forceinline__ uint32_t pack_half2(float lo, float hi) {
    __half2 h = __floats2half2_rn(lo, hi);
    return *reinterpret_cast<uint32_t*>(&h);
}
__device__ __forceinline__ void mma16816(float* c,
                                         uint32_t a0, uint32_t a1, uint32_t a2, uint32_t a3,
                                         uint32_t b0, uint32_t b1) {
    asm volatile("mma.sync.aligned.m16n8k16.row.col.f32.f16.f16.f32 "
                 "{%0,%1,%2,%3}, {%4,%5,%6,%7}, {%8,%9}, {%0,%1,%2,%3};"
                 : "+f"(c[0]), "+f"(c[1]), "+f"(c[2]), "+f"(c[3])
                 : "r"(a0), "r"(a1), "r"(a2), "r"(a3), "r"(b0), "r"(b1));
}

// ---------------- prep: z (B,K,H,W) int32 -> g_zt (I,J,B,K) fp16(z/15); weight packs ----------------
// blocks 0..1023: transpose, block = (i, b-chunk of 16). blocks 1024..1103: weights + counter reset.
__global__ void __launch_bounds__(256) prep_all(const int* __restrict__ z,
                                                const float* __restrict__ W1,
                                                const float* __restrict__ W2) {
    __shared__ __half tile[64 * 258];                 // [j][bb*16+k], row stride 258 halves (129 words, odd)
    if (blockIdx.x < 1024) {
        const int i  = blockIdx.x >> 4;
        const int bc = blockIdx.x & 15;               // b-chunk: b = bc*16 + bb
        const int t  = threadIdx.x;
        const int j  = t & 63;
        const int rg = t >> 6;                        // 0..3
        // phase 1: read z coalesced over j
#pragma unroll 8
        for (int r = 0; r < 64; r++) {
            int row = r * 4 + rg;                     // 0..255 = bb*16 + k
            int bb = row >> 4, k = row & 15;
            int b = bc * 16 + bb;
            int v = z[(size_t)b * 65536 + (size_t)k * 4096 + i * 64 + j];
            tile[j * 258 + bb * 16 + k] = __float2half((float)v * (1.0f / 15.0f));
        }
        __syncthreads();
        // phase 2: write g_zt coalesced (16B chunks)
        const uint32_t* sw = reinterpret_cast<const uint32_t*>(tile);
#pragma unroll
        for (int it = 0; it < 8; it++) {
            int c = it * 256 + t;                     // 0..2047
            int row2 = c >> 1, half = c & 1;
            int jo = row2 >> 4, bb = row2 & 15;
            uint4 v;
            const uint32_t* s = sw + jo * 129 + bb * 8 + half * 4;
            v.x = s[0]; v.y = s[1]; v.z = s[2]; v.w = s[3];
            uint32_t off = ((((uint32_t)i << 6) | (uint32_t)jo) << 8) + (uint32_t)(bc * 16 + bb);
            *reinterpret_cast<uint4*>(reinterpret_cast<char*>(g_zt) + ((size_t)off << 5) + half * 16) = v;
        }
    } else {
        const int tx = (blockIdx.x - 1024) * 256 + threadIdx.x;   // 0..20479
        if (tx == 0) { g_counter = 0; g_done = 0; }
        for (int idx = tx; idx < 147456; idx += 20480) {          // 16v x 72kp x 128m
            int v = idx / 9216;
            int r = idx - v * 9216;
            int kp = r >> 7, m = r & 127;
            int n = m >> 4, tt = m & 15;
            int h = 16 * (tt & 7) + 8 * (tt >> 3) + n;            // permuted h for (tile tt, col n)
            int drop = 64 + v;
            int f0 = 2 * kp, f1 = 2 * kp + 1;
            float x0 = (f0 == drop) ? 0.f : W1[(f0 - (f0 > drop)) * 128 + h];
            float x1 = (f1 == drop) ? 0.f : W1[(f1 - (f1 > drop)) * 128 + h];
            g_w1p[v * 9504 + kp * 132 + m] = pack_half2(x0, x1);
        }
        if (tx < 1024) {
            int kp = tx >> 4, c = tx & 15;
            g_w2p[tx] = pack_half2(W2[(2 * kp) * 16 + c], W2[(2 * kp + 1) * 16 + c]);
        }
    }
}

// ---------------- main kernel ----------------
// grid 1024 (one CTA per n). 8 warps, each warp owns M=32 b-rows (two m16 tiles).
__global__ void __launch_bounds__(256, 1)
main_kernel(const int* __restrict__ z, const int* __restrict__ bs,
            const int* __restrict__ ii, const int* __restrict__ jj,
            const float* __restrict__ b1, const float* __restrict__ b2,
            float* __restrict__ out)
{
    __shared__ __align__(16) uint32_t w1s[9504];   // [kp stride 132][m] — LDS.128 conflict-free
    __shared__ __align__(16) uint32_t w2s[1024];
    __shared__ float b1s[128];
    __shared__ float b2s[16];
    __shared__ int   ered[8];

    const int tid  = threadIdx.x;
    const int lane = tid & 31;
    const int wm   = tid >> 5;
    const int tig  = lane & 3;
    const int gid  = lane >> 2;
    const int n = blockIdx.x;

    const int bsv = __ldg(bs + n), iiv = __ldg(ii + n), jjv = __ldg(jj + n);

    // ---- stage weights/biases ----
    {
        const uint4* s1 = reinterpret_cast<const uint4*>(g_w1p) + bsv * 2376;
        uint4* d1 = reinterpret_cast<uint4*>(w1s);
        for (int i = tid; i < 2376; i += 256) d1[i] = s1[i];
        reinterpret_cast<uint4*>(w2s)[tid] = reinterpret_cast<const uint4*>(g_w2p)[tid];
        if (tid < 128) b1s[tid] = b1[tid];
        if (tid < 16)  b2s[tid] = b2[tid];
    }
    __syncthreads();

    // ---- MMA1: two m16 tiles per warp (rows b_lo..+8 and +16..+24), 16 N-tiles ----
    float c0[16][4], c1[16][4];
#pragma unroll
    for (int t = 0; t < 16; t++) {
#pragma unroll
        for (int q = 0; q < 4; q++) { c0[t][q] = 0.f; c1[t][q] = 0.f; }
    }

    const int b_lo = wm * 32 + gid;
    const unsigned char* zt = reinterpret_cast<const unsigned char*>(g_zt);

#pragma unroll
    for (int s = 0; s < 9; s++) {
        const int ni = (iiv + (s / 3) + 63) & 63;
        const int nj = (jjv + (s % 3) + 63) & 63;
        const unsigned char* p = zt
            + ((((uint32_t)ni << 6) | (uint32_t)nj) << 13)
            + ((uint32_t)b_lo << 5) + 4u * (uint32_t)tig;
        // A frags: one LDG.U32 each (k-pair adjacent in g_zt)
        uint32_t a0 = *reinterpret_cast<const uint32_t*>(p);
        uint32_t a2 = *reinterpret_cast<const uint32_t*>(p + 16);
        uint32_t a1 = *reinterpret_cast<const uint32_t*>(p + 8 * 32);
        uint32_t a3 = *reinterpret_cast<const uint32_t*>(p + 8 * 32 + 16);
        uint32_t e0 = *reinterpret_cast<const uint32_t*>(p + 16 * 32);
        uint32_t e2 = *reinterpret_cast<const uint32_t*>(p + 16 * 32 + 16);
        uint32_t e1 = *reinterpret_cast<const uint32_t*>(p + 24 * 32);
        uint32_t e3 = *reinterpret_cast<const uint32_t*>(p + 24 * 32 + 16);

        const uint32_t krow = (8u * s + (uint32_t)tig) * 132u + 16u * (uint32_t)gid;
        const uint4* w0p = reinterpret_cast<const uint4*>(w1s + krow);
        const uint4* w4p = reinterpret_cast<const uint4*>(w1s + krow + 528);
#pragma unroll
        for (int q = 0; q < 4; q++) {
            uint4 lo = w0p[q];                 // bb0 for tiles 4q..4q+3
            uint4 hi = w4p[q];                 // bb1 for tiles 4q..4q+3
            mma16816(c0[4 * q + 0], a0, a1, a2, a3, lo.x, hi.x);
            mma16816(c1[4 * q + 0], e0, e1, e2, e3, lo.x, hi.x);
            mma16816(c0[4 * q + 1], a0, a1, a2, a3, lo.y, hi.y);
            mma16816(c1[4 * q + 1], e0, e1, e2, e3, lo.y, hi.y);
            mma16816(c0[4 * q + 2], a0, a1, a2, a3, lo.z, hi.z);
            mma16816(c1[4 * q + 2], e0, e1, e2, e3, lo.z, hi.z);
            mma16816(c0[4 * q + 3], a0, a1, a2, a3, lo.w, hi.w);
            mma16816(c1[4 * q + 3], e0, e1, e2, e3, lo.w, hi.w);
        }
    }

    // ---- layer 2: h = relu(c + b1) chained as A-frags (tile s2 -> cols h=16s2+2tig, tile s2+8 -> +8) ----
    float dA0[4] = {0.f, 0.f, 0.f, 0.f}, dA1[4] = {0.f, 0.f, 0.f, 0.f};
    float dB0[4] = {0.f, 0.f, 0.f, 0.f}, dB1[4] = {0.f, 0.f, 0.f, 0.f};
    const float2* b1f2 = reinterpret_cast<const float2*>(b1s);
#pragma unroll
    for (int s2 = 0; s2 < 8; s2++) {
        float2 bA = b1f2[8 * s2 + tig];        // bias for h = 16*s2 + 2*tig, +1
        float2 bB = b1f2[8 * s2 + 4 + tig];    // bias for h = 16*s2 + 8 + 2*tig, +1
        const int tA = s2, tB = s2 + 8;
        uint32_t a0 = pack_half2(fmaxf(c0[tA][0] + bA.x, 0.f), fmaxf(c0[tA][1] + bA.y, 0.f));
        uint32_t a1 = pack_half2(fmaxf(c0[tA][2] + bA.x, 0.f), fmaxf(c0[tA][3] + bA.y, 0.f));
        uint32_t a2 = pack_half2(fmaxf(c0[tB][0] + bB.x, 0.f), fmaxf(c0[tB][1] + bB.y, 0.f));
        uint32_t a3 = pack_half2(fmaxf(c0[tB][2] + bB.x, 0.f), fmaxf(c0[tB][3] + bB.y, 0.f));
        uint32_t e0 = pack_half2(fmaxf(c1[tA][0] + bA.x, 0.f), fmaxf(c1[tA][1] + bA.y, 0.f));
        uint32_t e1 = pack_half2(fmaxf(c1[tA][2] + bA.x, 0.f), fmaxf(c1[tA][3] + bA.y, 0.f));
        uint32_t e2 = pack_half2(fmaxf(c1[tB][0] + bB.x, 0.f), fmaxf(c1[tB][1] + bB.y, 0.f));
        uint32_t e3 = pack_half2(fmaxf(c1[tB][2] + bB.x, 0.f), fmaxf(c1[tB][3] + bB.y, 0.f));

        uint32_t b00 = w2s[(8 * s2 + tig) * 16 + gid];
        uint32_t b01 = w2s[(8 * s2 + tig + 4) * 16 + gid];
        uint32_t b10 = w2s[(8 * s2 + tig) * 16 + 8 + gid];
        uint32_t b11 = w2s[(8 * s2 + tig + 4) * 16 + 8 + gid];
        mma16816(dA0, a0, a1, a2, a3, b00, b01);
        mma16816(dA1, a0, a1, a2, a3, b10, b11);
        mma16816(dB0, e0, e1, e2, e3, b00, b01);
        mma16816(dB1, e0, e1, e2, e3, b10, b11);
    }

    // ---- epilogue: argmax per row (4 rows per thread-group), count errors ----
    float2 q0 = reinterpret_cast<const float2*>(b2s)[tig];       // classes 2tig, 2tig+1
    float2 q1 = reinterpret_cast<const float2*>(b2s)[tig + 4];   // classes 8+2tig, 9+2tig

    float bv[4]; int bi[4];
    {
        const float* d0[2] = { dA0, dB0 };
        const float* d1[2] = { dA1, dB1 };
#pragma unroll
        for (int tb = 0; tb < 2; tb++) {
#pragma unroll
            for (int hr = 0; hr < 2; hr++) {
                float v0 = d0[tb][2 * hr]     + q0.x;
                float v1 = d0[tb][2 * hr + 1] + q0.y;
                float v2 = d1[tb][2 * hr]     + q1.x;
                float v3 = d1[tb][2 * hr + 1] + q1.y;
                float best = v0; int idx = 2 * tig;
                if (v1 > best) { best = v1; idx = 2 * tig + 1; }
                if (v2 > best) { best = v2; idx = 8 + 2 * tig; }
                if (v3 > best) { best = v3; idx = 9 + 2 * tig; }
                bv[tb * 2 + hr] = best; bi[tb * 2 + hr] = idx;
            }
        }
    }
#pragma unroll
    for (int off = 1; off <= 2; off <<= 1) {
#pragma unroll
        for (int r = 0; r < 4; r++) {
            float ov = __shfl_xor_sync(0xffffffffu, bv[r], off);
            int   oi = __shfl_xor_sync(0xffffffffu, bi[r], off);
            if (ov > bv[r] || (ov == bv[r] && oi < bi[r])) { bv[r] = ov; bi[r] = oi; }
        }
    }

    unsigned errs = 0;
    if (tig == 0) {
        const size_t toff = (size_t)bsv * 4096 + (size_t)iiv * 64 + jjv;
        int t0 = __ldg(z + ((size_t)(b_lo)      << 16) + toff);
        int t1 = __ldg(z + ((size_t)(b_lo + 8)  << 16) + toff);
        int t2 = __ldg(z + ((size_t)(b_lo + 16) << 16) + toff);
        int t3 = __ldg(z + ((size_t)(b_lo + 24) << 16) + toff);
        errs = (unsigned)(bi[0] != t0) + (unsigned)(bi[1] != t1)
             + (unsigned)(bi[2] != t2) + (unsigned)(bi[3] != t3);
    }
    unsigned wtot = __reduce_add_sync(0xffffffffu, errs);
    if (lane == 0) ered[wm] = (int)wtot;
    __syncthreads();
    if (tid == 0) {
        int tot = 0;
#pragma unroll
        for (int w = 0; w < 8; w++) tot += ered[w];
        atomicAdd(&g_counter, tot);
        __threadfence();
        int done = atomicAdd(&g_done, 1);
        if (done == (int)gridDim.x - 1) {
            int cnt = atomicAdd(&g_counter, 0);
            out[0] = (float)cnt * (1.0f / 262144.0f);     // N*B = 2^18
        }
    }
}

// ---------------- launch ----------------
extern "C" void kernel_launch(void* const* d_in, const int* in_sizes, int n_in,
                              void* d_out, int out_size) {
    (void)in_sizes; (void)n_in; (void)out_size;
    const int*   z  = (const int*)d_in[0];
    const int*   bs = (const int*)d_in[1];
    const int*   ii = (const int*)d_in[2];
    const int*   jj = (const int*)d_in[3];
    const float* W1 = (const float*)d_in[4];
    const float* b1 = (const float*)d_in[5];
    const float* W2 = (const float*)d_in[6];
    const float* b2 = (const float*)d_in[7];

    prep_all<<<1104, 256>>>(z, W1, W2);
    main_kernel<<<1024, 256>>>(z, bs, ii, jj, b1, b2, (float*)d_out);
}

// round 15
// speedup vs baseline: 1.0978x; 1.0284x over previous
#include <cuda_runtime.h>
#include <cuda_fp16.h>
#include <cstdint>
#include <cstddef>

// ---------------- problem constants ----------------
// B=256, K=16, H=64, W=64, N=1024, F_IN=143 (=144 with zero drop), HID=128, NCLS=16

// ---------------- device scratch ----------------
__device__ __align__(16) __half   g_zt[64u * 64u * 256u * 16u];  // (i,j,b,k) fp16 of z/15 — k fastest (32B rows)
__device__ __align__(16) uint32_t g_w1p[16 * 9504];              // [v][kp<72, stride 132][m<128] permuted W1 packs
__device__ __align__(16) uint32_t g_w2p[1024];                   // [kp<64][c<16] half2
__device__ int g_counter;
__device__ int g_done;

// ---------------- helpers ----------------
__device__ __forceinline__ uint32_t pack_half2(float lo, float hi) {
    __half2 h = __floats2half2_rn(lo, hi);
    return *reinterpret_cast<uint32_t*>(&h);
}
__device__ __forceinline__ void mma16816(float* c,
                                         uint32_t a0, uint32_t a1, uint32_t a2, uint32_t a3,
                                         uint32_t b0, uint32_t b1) {
    asm volatile("mma.sync.aligned.m16n8k16.row.col.f32.f16.f16.f32 "
                 "{%0,%1,%2,%3}, {%4,%5,%6,%7}, {%8,%9}, {%0,%1,%2,%3};"
                 : "+f"(c[0]), "+f"(c[1]), "+f"(c[2]), "+f"(c[3])
                 : "r"(a0), "r"(a1), "r"(a2), "r"(a3), "r"(b0), "r"(b1));
}

// ---------------- prep: z (B,K,H,W) int32 -> g_zt (I,J,B,K) fp16(z/15); weight packs ----------------
__global__ void __launch_bounds__(256) prep_all(const int* __restrict__ z,
                                                const float* __restrict__ W1,
                                                const float* __restrict__ W2) {
    __shared__ __half tile[64 * 258];
    if (blockIdx.x < 1024) {
        const int i  = blockIdx.x >> 4;
        const int bc = blockIdx.x & 15;
        const int t  = threadIdx.x;
        const int j  = t & 63;
        const int rg = t >> 6;
#pragma unroll 8
        for (int r = 0; r < 64; r++) {
            int row = r * 4 + rg;
            int bb = row >> 4, k = row & 15;
            int b = bc * 16 + bb;
            int v = z[(size_t)b * 65536 + (size_t)k * 4096 + i * 64 + j];
            tile[j * 258 + bb * 16 + k] = __float2half((float)v * (1.0f / 15.0f));
        }
        __syncthreads();
        const uint32_t* sw = reinterpret_cast<const uint32_t*>(tile);
#pragma unroll
        for (int it = 0; it < 8; it++) {
            int c = it * 256 + t;
            int row2 = c >> 1, half = c & 1;
            int jo = row2 >> 4, bb = row2 & 15;
            uint4 v;
            const uint32_t* s = sw + jo * 129 + bb * 8 + half * 4;
            v.x = s[0]; v.y = s[1]; v.z = s[2]; v.w = s[3];
            uint32_t off = ((((uint32_t)i << 6) | (uint32_t)jo) << 8) + (uint32_t)(bc * 16 + bb);
            *reinterpret_cast<uint4*>(reinterpret_cast<char*>(g_zt) + ((size_t)off << 5) + half * 16) = v;
        }
    } else {
        const int tx = (blockIdx.x - 1024) * 256 + threadIdx.x;
        if (tx == 0) { g_counter = 0; g_done = 0; }
        for (int idx = tx; idx < 147456; idx += 20480) {          // 16v x 72kp x 128m
            int v = idx / 9216;
            int r = idx - v * 9216;
            int kp = r >> 7, m = r & 127;
            int n = m >> 4, tt = m & 15;
            int h = 16 * (tt & 7) + 8 * (tt >> 3) + n;
            int drop = 64 + v;
            int f0 = 2 * kp, f1 = 2 * kp + 1;
            float x0 = (f0 == drop) ? 0.f : W1[(f0 - (f0 > drop)) * 128 + h];
            float x1 = (f1 == drop) ? 0.f : W1[(f1 - (f1 > drop)) * 128 + h];
            g_w1p[v * 9504 + kp * 132 + m] = pack_half2(x0, x1);
        }
        if (tx < 1024) {
            int kp = tx >> 4, c = tx & 15;
            g_w2p[tx] = pack_half2(W2[(2 * kp) * 16 + c], W2[(2 * kp + 1) * 16 + c]);
        }
    }
}

// ---------------- main kernel ----------------
// grid (1024, 2): n = blockIdx.x, b-half = blockIdx.y (128 rows). 8 warps.
// Layer 1: warp wm = hh*4 + wb: b-group wb (32 rows), h-half hh (64 hidden).
// Layer 2: warp wm owns m16 tile wm (rows 16*wm..+15), h from SMEM buffer.
static constexpr uint32_t OFF_W1 = 0;         // 9504 words (38016 B)
static constexpr uint32_t OFF_W2 = 38016;     // 1024 words (4096 B)
static constexpr uint32_t OFF_HB = 42112;     // h-buffer: 128 rows x 272 B (stride 68 words)
static constexpr uint32_t OFF_B1 = 76928;     // 128 floats
static constexpr uint32_t OFF_B2 = 77440;     // 16 floats
static constexpr uint32_t OFF_ER = 77504;     // 8 ints
static constexpr uint32_t SMEM_BYTES = 77536;

__global__ void __launch_bounds__(256, 2)
main_kernel(const int* __restrict__ z, const int* __restrict__ bs,
            const int* __restrict__ ii, const int* __restrict__ jj,
            const float* __restrict__ b1, const float* __restrict__ b2,
            float* __restrict__ out)
{
    extern __shared__ __align__(16) char dsm[];
    uint32_t* w1s = reinterpret_cast<uint32_t*>(dsm + OFF_W1);
    uint32_t* w2s = reinterpret_cast<uint32_t*>(dsm + OFF_W2);
    uint32_t* hb  = reinterpret_cast<uint32_t*>(dsm + OFF_HB);
    float*    b1s = reinterpret_cast<float*>(dsm + OFF_B1);
    float*    b2s = reinterpret_cast<float*>(dsm + OFF_B2);
    int*      ered = reinterpret_cast<int*>(dsm + OFF_ER);

    const int tid  = threadIdx.x;
    const int lane = tid & 31;
    const int wm   = tid >> 5;
    const int tig  = lane & 3;
    const int gid  = lane >> 2;
    const int hh   = wm >> 2;              // h-half (layer 1)
    const int wb   = wm & 3;               // b-group (layer 1)
    const int n = blockIdx.x, bhalf = blockIdx.y;

    const int bsv = __ldg(bs + n), iiv = __ldg(ii + n), jjv = __ldg(jj + n);

    // ---- stage weights/biases ----
    {
        const uint4* s1 = reinterpret_cast<const uint4*>(g_w1p) + bsv * 2376;
        uint4* d1 = reinterpret_cast<uint4*>(w1s);
        for (int i = tid; i < 2376; i += 256) d1[i] = s1[i];
        reinterpret_cast<uint4*>(w2s)[tid] = reinterpret_cast<const uint4*>(g_w2p)[tid];
        if (tid < 128) b1s[tid] = b1[tid];
        if (tid < 16)  b2s[tid] = b2[tid];
    }
    __syncthreads();

    // ---- layer 1: 8 local N-tiles (u=0..7 of half hh), rows 32*wb..+31 ----
    float c0[8][4], c1[8][4];
#pragma unroll
    for (int t = 0; t < 8; t++) {
#pragma unroll
        for (int q = 0; q < 4; q++) { c0[t][q] = 0.f; c1[t][q] = 0.f; }
    }

    const int b_loc = wb * 32 + gid;                       // local row (0..127)
    const int b_glo = bhalf * 128 + b_loc;                 // global b
    const unsigned char* zt = reinterpret_cast<const unsigned char*>(g_zt);

#pragma unroll
    for (int s = 0; s < 9; s++) {
        const int ni = (iiv + (s / 3) + 63) & 63;
        const int nj = (jjv + (s % 3) + 63) & 63;
        const unsigned char* p = zt
            + ((((uint32_t)ni << 6) | (uint32_t)nj) << 13)
            + ((uint32_t)b_glo << 5) + 4u * (uint32_t)tig;
        uint32_t a0 = *reinterpret_cast<const uint32_t*>(p);
        uint32_t a2 = *reinterpret_cast<const uint32_t*>(p + 16);
        uint32_t a1 = *reinterpret_cast<const uint32_t*>(p + 8 * 32);
        uint32_t a3 = *reinterpret_cast<const uint32_t*>(p + 8 * 32 + 16);
        uint32_t e0 = *reinterpret_cast<const uint32_t*>(p + 16 * 32);
        uint32_t e2 = *reinterpret_cast<const uint32_t*>(p + 16 * 32 + 16);
        uint32_t e1 = *reinterpret_cast<const uint32_t*>(p + 24 * 32);
        uint32_t e3 = *reinterpret_cast<const uint32_t*>(p + 24 * 32 + 16);

        const uint32_t krow = (8u * s + (uint32_t)tig) * 132u + 16u * (uint32_t)gid + 8u * (uint32_t)hh;
        const uint4* w0p = reinterpret_cast<const uint4*>(w1s + krow);
        const uint4* w4p = reinterpret_cast<const uint4*>(w1s + krow + 528);
#pragma unroll
        for (int q = 0; q < 2; q++) {
            uint4 lo = w0p[q];
            uint4 hi = w4p[q];
            mma16816(c0[4 * q + 0], a0, a1, a2, a3, lo.x, hi.x);
            mma16816(c1[4 * q + 0], e0, e1, e2, e3, lo.x, hi.x);
            mma16816(c0[4 * q + 1], a0, a1, a2, a3, lo.y, hi.y);
            mma16816(c1[4 * q + 1], e0, e1, e2, e3, lo.y, hi.y);
            mma16816(c0[4 * q + 2], a0, a1, a2, a3, lo.z, hi.z);
            mma16816(c1[4 * q + 2], e0, e1, e2, e3, lo.z, hi.z);
            mma16816(c0[4 * q + 3], a0, a1, a2, a3, lo.w, hi.w);
            mma16816(c1[4 * q + 3], e0, e1, e2, e3, lo.w, hi.w);
        }
    }

    // ---- relu(c + b1) -> fp16 h-buffer [row 0..127][h-pair], stride 68 words ----
    {
        const float2* b1f2 = reinterpret_cast<const float2*>(b1s);
#pragma unroll
        for (int u = 0; u < 8; u++) {
            // tile u of half hh -> h = 16u + 8hh + n (n = 2tig, 2tig+1)
            float2 bb = b1f2[8 * u + 4 * hh + tig];
            const uint32_t col = 8u * u + 4u * (uint32_t)hh + (uint32_t)tig;
            hb[(uint32_t)(b_loc)      * 68u + col] = pack_half2(fmaxf(c0[u][0] + bb.x, 0.f), fmaxf(c0[u][1] + bb.y, 0.f));
            hb[(uint32_t)(b_loc + 8)  * 68u + col] = pack_half2(fmaxf(c0[u][2] + bb.x, 0.f), fmaxf(c0[u][3] + bb.y, 0.f));
            hb[(uint32_t)(b_loc + 16) * 68u + col] = pack_half2(fmaxf(c1[u][0] + bb.x, 0.f), fmaxf(c1[u][1] + bb.y, 0.f));
            hb[(uint32_t)(b_loc + 24) * 68u + col] = pack_half2(fmaxf(c1[u][2] + bb.x, 0.f), fmaxf(c1[u][3] + bb.y, 0.f));
        }
    }
    __syncthreads();

    // ---- layer 2: warp wm -> m16 tile (rows 16*wm..+15), K=128 (8 steps) ----
    float dA0[4] = {0.f, 0.f, 0.f, 0.f}, dA1[4] = {0.f, 0.f, 0.f, 0.f};
    const int r0 = 16 * wm + gid;
#pragma unroll
    for (int s2 = 0; s2 < 8; s2++) {
        uint32_t a0 = hb[(uint32_t)r0 * 68u + 8u * s2 + tig];
        uint32_t a1 = hb[(uint32_t)(r0 + 8) * 68u + 8u * s2 + tig];
        uint32_t a2 = hb[(uint32_t)r0 * 68u + 8u * s2 + 4u + tig];
        uint32_t a3 = hb[(uint32_t)(r0 + 8) * 68u + 8u * s2 + 4u + tig];

        uint32_t b00 = w2s[(8 * s2 + tig) * 16 + gid];
        uint32_t b01 = w2s[(8 * s2 + tig + 4) * 16 + gid];
        uint32_t b10 = w2s[(8 * s2 + tig) * 16 + 8 + gid];
        uint32_t b11 = w2s[(8 * s2 + tig + 4) * 16 + 8 + gid];
        mma16816(dA0, a0, a1, a2, a3, b00, b01);
        mma16816(dA1, a0, a1, a2, a3, b10, b11);
    }

    // ---- epilogue: argmax over 16 classes for rows r0, r0+8 ----
    float2 q0 = reinterpret_cast<const float2*>(b2s)[tig];
    float2 q1 = reinterpret_cast<const float2*>(b2s)[tig + 4];

    float bv[2]; int bi[2];
#pragma unroll
    for (int hr = 0; hr < 2; hr++) {
        float v0 = dA0[2 * hr]     + q0.x;
        float v1 = dA0[2 * hr + 1] + q0.y;
        float v2 = dA1[2 * hr]     + q1.x;
        float v3 = dA1[2 * hr + 1] + q1.y;
        float best = v0; int idx = 2 * tig;
        if (v1 > best) { best = v1; idx = 2 * tig + 1; }
        if (v2 > best) { best = v2; idx = 8 + 2 * tig; }
        if (v3 > best) { best = v3; idx = 9 + 2 * tig; }
        bv[hr] = best; bi[hr] = idx;
    }
#pragma unroll
    for (int off = 1; off <= 2; off <<= 1) {
#pragma unroll
        for (int r = 0; r < 2; r++) {
            float ov = __shfl_xor_sync(0xffffffffu, bv[r], off);
            int   oi = __shfl_xor_sync(0xffffffffu, bi[r], off);
            if (ov > bv[r] || (ov == bv[r] && oi < bi[r])) { bv[r] = ov; bi[r] = oi; }
        }
    }

    unsigned errs = 0;
    if (tig == 0) {
        const size_t toff = (size_t)bsv * 4096 + (size_t)iiv * 64 + jjv;
        const int g0 = bhalf * 128 + r0;
        int t0 = __ldg(z + ((size_t)g0       << 16) + toff);
        int t1 = __ldg(z + ((size_t)(g0 + 8) << 16) + toff);
        errs = (unsigned)(bi[0] != t0) + (unsigned)(bi[1] != t1);
    }
    unsigned wtot = __reduce_add_sync(0xffffffffu, errs);
    if (lane == 0) ered[wm] = (int)wtot;
    __syncthreads();
    if (tid == 0) {
        int tot = 0;
#pragma unroll
        for (int w = 0; w < 8; w++) tot += ered[w];
        atomicAdd(&g_counter, tot);
        __threadfence();
        int done = atomicAdd(&g_done, 1);
        if (done == (int)(gridDim.x * gridDim.y) - 1) {
            int cnt = atomicAdd(&g_counter, 0);
            out[0] = (float)cnt * (1.0f / 262144.0f);     // N*B = 2^18
        }
    }
}

// ---------------- launch ----------------
extern "C" void kernel_launch(void* const* d_in, const int* in_sizes, int n_in,
                              void* d_out, int out_size) {
    (void)in_sizes; (void)n_in; (void)out_size;
    const int*   z  = (const int*)d_in[0];
    const int*   bs = (const int*)d_in[1];
    const int*   ii = (const int*)d_in[2];
    const int*   jj = (const int*)d_in[3];
    const float* W1 = (const float*)d_in[4];
    const float* b1 = (const float*)d_in[5];
    const float* W2 = (const float*)d_in[6];
    const float* b2 = (const float*)d_in[7];

    static int smem_set = 0;
    if (!smem_set) {
        cudaFuncSetAttribute(main_kernel, cudaFuncAttributeMaxDynamicSharedMemorySize, SMEM_BYTES);
        smem_set = 1;
    }

    prep_all<<<1104, 256>>>(z, W1, W2);
    main_kernel<<<dim3(1024, 2), 256, SMEM_BYTES>>>(z, bs, ii, jj, b1, b2, (float*)d_out);
}